// round 17
// baseline (speedup 1.0000x reference)
#include <cuda_runtime.h>
#include <cstdint>

#define G_    8
#define FG_   16
#define J_    8
#define W_    31
#define PAD1_ 15
#define L_    262144
#define KTILE_ 512
#define NTH_  256

// SMEM (32-bit words). Per j: copy0[272] fp16x2 pairs (2w,2w+1),
// copy1[272] pairs (2w+1,2w+2); copy1 at +272 words = +16 banks.
#define XS_PITCH 548
#define XS_ELEMS (J_ * XS_PITCH)          // 4384
// ws: [j][w0g][lane] uint4 = {b0_nh0, b1_nh0, b0_nh1, b1_nh1} fp16x2 each
#define WS_ELEMS (J_ * 2 * 32 * 4)        // 2048 words
#define SM_XS 0
#define SM_WS (SM_XS + XS_ELEMS)          // 4384
#define SMEM_WORDS (SM_WS + WS_ELEMS)     // 6432 words = 25728 B

// Pre-transformed fp16 weight image: [g][j][w0g][lane] uint4, 64 KB.
__device__ uint32_t d_wt[G_ * WS_ELEMS];

__device__ __forceinline__ uint32_t pack_h2(float lo, float hi) {
    uint32_t r;
    asm("cvt.rn.f16x2.f32 %0, %1, %2;" : "=r"(r) : "f"(hi), "f"(lo));
    return r;
}
__device__ __forceinline__ void cp16(uint32_t dst_smem, const void* src) {
    asm volatile("cp.async.cg.shared.global [%0], [%1], 16;"
                 :: "r"(dst_smem), "l"(src) : "memory");
}

__device__ __forceinline__ void mma_f16(float d[4],
                                        uint32_t a0, uint32_t a1,
                                        uint32_t a2, uint32_t a3,
                                        uint32_t b0, uint32_t b1) {
    asm volatile(
        "mma.sync.aligned.m16n8k16.row.col.f32.f16.f16.f32 "
        "{%0,%1,%2,%3}, {%4,%5,%6,%7}, {%8,%9}, {%0,%1,%2,%3};"
        : "+f"(d[0]), "+f"(d[1]), "+f"(d[2]), "+f"(d[3])
        : "r"(a0), "r"(a1), "r"(a2), "r"(a3), "r"(b0), "r"(b1));
}

// Prep: params [g][f][j][w] -> fp16 B-fragment image.
__global__ void prep_w(const float* __restrict__ params) {
    int idx = blockIdx.x * blockDim.x + threadIdx.x;
    if (idx >= G_ * J_ * 2 * 32) return;
    int lane = idx & 31;
    int w0g  = (idx >> 5) & 1;
    int j    = (idx >> 6) & 7;
    int g    = idx >> 9;
    int gidl = lane >> 2;
    int w    = 16 * w0g + 2 * (lane & 3);
    auto Wv = [&](int f, int ww) -> float {
        return (ww < W_) ? params[((g * FG_ + f) * J_ + j) * W_ + ww] : 0.f;
    };
    uint4 o;
    o.x = pack_h2(Wv(gidl, w),         Wv(gidl, w + 1));
    o.y = pack_h2(Wv(gidl, w + 8),     Wv(gidl, w + 9));
    o.z = pack_h2(Wv(gidl + 8, w),     Wv(gidl + 8, w + 1));
    o.w = pack_h2(Wv(gidl + 8, w + 8), Wv(gidl + 8, w + 9));
    *(uint4*)(d_wt + idx * 4) = o;
}

// CTA: group g, 512 consecutive k, 16 filters. Warp: 64 k x 16 f.
// fp16 m16n8k16; Toeplitz A; SLIDING 5-reg X window (2 fresh LDS per mi)
// to cut live registers -> 5 CTAs/SM.
__global__ void __launch_bounds__(NTH_, 5)
conv_mma(const float* __restrict__ x,
         const float* __restrict__ params,
         const int* __restrict__ rel,
         float* __restrict__ out)
{
    extern __shared__ uint32_t sm[];
    const uint32_t smb = (uint32_t)__cvta_generic_to_shared(sm);
    const int tid  = threadIdx.x;
    const int wid  = tid >> 5;
    const int lane = tid & 31;
    const int gid  = lane >> 2;
    const int tig  = lane & 3;
    const int g    = blockIdx.y;
    const int tile = blockIdx.x;
    const int kb   = tile * KTILE_;
    const int last = L_ / KTILE_ - 1;
    const bool interior = (tile != 0) && (tile != last);

    int rows[J_];
#pragma unroll
    for (int j = 0; j < J_; ++j) rows[j] = __ldg(rel + g * J_ + j);

    // ---- weights: 8 KB cp.async from prep image ----
    {
        const uint32_t* src = d_wt + g * WS_ELEMS;
#pragma unroll
        for (int e = tid; e < WS_ELEMS / 4; e += NTH_)
            cp16(smb + (SM_WS + e * 4) * 4, src + e * 4);
        asm volatile("cp.async.commit_group;" ::: "memory");
    }

    // ---- x windows: win[s] = x[kb + s - 16], s in [0,544) as fp16 pairs ----
    if (interior) {
#pragma unroll 1
        for (int j = 0; j < J_; ++j) {
            const float*  xe  = x + rows[j] * L_ + kb - 16;
            const float4* xp4 = (const float4*)xe;
            uint32_t* row = sm + SM_XS + j * XS_PITCH;
            for (int q = tid; q < 136; q += NTH_) {
                float4 v = __ldg(xp4 + q);
                float x4 = __ldg(xe + 4 * q + 4);
                uint2 c0, c1;
                c0.x = pack_h2(v.x, v.y);  c0.y = pack_h2(v.z, v.w);
                c1.x = pack_h2(v.y, v.z);  c1.y = pack_h2(v.w, x4);
                *(uint2*)(row + 2 * q)       = c0;
                *(uint2*)(row + 272 + 2 * q) = c1;
            }
        }
    } else {
        // edge tiles: clamped scalar path (pollutes only overwritten outputs)
#pragma unroll 1
        for (int j = 0; j < J_; ++j) {
            const float* xr = x + rows[j] * L_;
            uint32_t* row = sm + SM_XS + j * XS_PITCH;
            for (int w = tid; w < 272; w += NTH_) {
                int s0 = kb + 2 * w - 16;
                float v0 = __ldg(xr + max(0, min(L_ - 1, s0)));
                float v1 = __ldg(xr + max(0, min(L_ - 1, s0 + 1)));
                float v2 = __ldg(xr + max(0, min(L_ - 1, s0 + 2)));
                row[w]       = pack_h2(v0, v1);
                row[272 + w] = pack_h2(v1, v2);
            }
        }
    }
    asm volatile("cp.async.wait_group 0;" ::: "memory");
    __syncthreads();

    const int warpk = wid * 64;

    float acc[4][2][4];
#pragma unroll
    for (int mi = 0; mi < 4; ++mi)
#pragma unroll
        for (int nh = 0; nh < 2; ++nh)
#pragma unroll
            for (int q = 0; q < 4; ++q) acc[mi][nh][q] = 0.f;

    // per-lane A window base: half-position h0 = warpk + 1 + gid + 2*tig
    const int h0 = warpk + 1 + gid + 2 * tig;
    const int P  = h0 & 1;
    const int wb = (h0 - P) >> 1;

#pragma unroll 1
    for (int j = 0; j < J_; ++j) {
        const uint32_t* xw = sm + SM_XS + j * XS_PITCH + P * 272 + wb;
        const uint4* wj = (const uint4*)(sm + SM_WS + j * 256) + lane;

        uint4 B0 = wj[0];
        uint4 B1 = wj[32];

        // sliding window: Xs[0..4] = pairs at u = 2mi .. 2mi+4
        uint32_t Xs[5];
#pragma unroll
        for (int u = 0; u < 5; ++u) Xs[u] = xw[4 * u];

#pragma unroll
        for (int mi = 0; mi < 4; ++mi) {
            // per-acc order (w0g=0 then w0g=1) identical to previous rounds
            mma_f16(acc[mi][0], Xs[0], Xs[1], Xs[1], Xs[2], B0.x, B0.y);
            mma_f16(acc[mi][1], Xs[0], Xs[1], Xs[1], Xs[2], B0.z, B0.w);
            mma_f16(acc[mi][0], Xs[2], Xs[3], Xs[3], Xs[4], B1.x, B1.y);
            mma_f16(acc[mi][1], Xs[2], Xs[3], Xs[3], Xs[4], B1.z, B1.w);
            if (mi < 3) {
                Xs[0] = Xs[2];
                Xs[1] = Xs[3];
                Xs[2] = Xs[4];
                Xs[3] = xw[4 * (2 * mi + 5)];
                Xs[4] = xw[4 * (2 * mi + 6)];
            }
        }
    }

    // ---- direct fragment store: perfectly coalesced STG.32 ----
    // d0:(k0,f0) d1:(k0,f0+1) d2:(k0+8,f0) d3:(k0+8,f0+1);
    // k0 = warpk+16mi+gid, f0 = nh*8+2tig
    {
        float* ob = out + g * FG_ * L_ + kb + warpk;
#pragma unroll
        for (int mi = 0; mi < 4; ++mi) {
#pragma unroll
            for (int nh = 0; nh < 2; ++nh) {
                const int f0 = nh * 8 + 2 * tig;
                float* o0 = ob + f0 * L_ + 16 * mi + gid;
                o0[0]      = acc[mi][nh][0];
                o0[L_]     = acc[mi][nh][1];
                o0[8]      = acc[mi][nh][2];
                o0[L_ + 8] = acc[mi][nh][3];
            }
        }
    }

    // ---- boundary overwrite (reference truncates; no zero-pad), full fp32 ----
    if (!interior) {
        __syncthreads();
        if (tid < FG_ * PAD1_) {
            const int f = tid / PAD1_;
            const int e = tid % PAD1_;
            const float* pk = params + (g * FG_ + f) * (J_ * W_);
            float s = 0.f;
            if (tile == 0) {
                for (int j = 0; j < J_; ++j) {
                    const float* xr = x + __ldg(rel + g * J_ + j) * L_;
                    for (int w = 0; w <= e + PAD1_; ++w)
                        s += xr[w] * pk[j * W_ + w];
                }
                out[(g * FG_ + f) * L_ + e] = s;
            } else {
                for (int j = 0; j < J_; ++j) {
                    const float* xr = x + __ldg(rel + g * J_ + j) * L_;
                    for (int w = e + 1; w < W_; ++w)
                        s += xr[L_ - W_ + w] * pk[j * W_ + w];
                }
                out[(g * FG_ + f) * L_ + (L_ - PAD1_ + e)] = s;
            }
        }
    }
}

extern "C" void kernel_launch(void* const* d_in, const int* in_sizes, int n_in,
                              void* d_out, int out_size)
{
    const float* x      = (const float*)d_in[0];
    const float* params = (const float*)d_in[1];
    const int*   rel    = (const int*)d_in[2];
    float* out = (float*)d_out;

    prep_w<<<(G_ * J_ * 2 * 32 + 255) / 256, 256>>>(params);

    cudaFuncSetAttribute(conv_mma, cudaFuncAttributeMaxDynamicSharedMemorySize,
                         SMEM_WORDS * 4);
    dim3 grid(L_ / KTILE_, G_);   // 512 x 8
    conv_mma<<<grid, NTH_, SMEM_WORDS * 4>>>(x, params, rel, out);
}